// round 1
// baseline (speedup 1.0000x reference)
#include <cuda_runtime.h>

// HashGridEncoder2D: L=16 levels, F=2, N=1048576 points, T=524288.
// Levels 0..11 dense, 12..15 hashed with prime 131101, mod 2^19.
// Thread layout: 8 threads per point; thread j handles levels 2j and 2j+1,
// producing 4 contiguous output floats -> one coalesced float4 store.

#define NPTS    1048576
#define TSIZE   524288
#define HPRIME  131101

__constant__ int c_res[16] = {16, 22, 30, 42, 58, 80, 111, 153,
                              212, 294, 406, 561, 776, 1072, 1482, 2048};
__constant__ int c_off[16] = {0, 289, 818, 1779, 3628, 7109, 13670, 26214,
                              49930, 95299, 182324, 347973,
                              663817, 1188105, 1712393, 2236681};

__global__ void __launch_bounds__(256)
hashgrid2d_kernel(const float2* __restrict__ uv,
                  const float2* __restrict__ lat,
                  float4* __restrict__ out)
{
    int t = blockIdx.x * blockDim.x + threadIdx.x;
    int n = t >> 3;          // point index
    int j = t & 7;           // level-pair index (levels 2j, 2j+1)
    if (n >= NPTS) return;

    float2 p = __ldg(&uv[n]);

    float r[4];

#pragma unroll
    for (int k = 0; k < 2; k++) {
        int l   = 2 * j + k;
        int res = c_res[l];
        int off = c_off[l];

        float fres = (float)res;
        float sx = p.x * fres;
        float sy = p.y * fres;
        float fx = floorf(sx);
        float fy = floorf(sy);
        int   x0 = (int)fx;
        int   y0 = (int)fy;
        float px = sx - fx;
        float py = sy - fy;

        int i00, i01, i10, i11;
        if (l >= 12) {
            // hashed: (x*1) ^ (y*PRIME) mod 2^19
            int hy0 = y0 * HPRIME;
            int hy1 = (y0 + 1) * HPRIME;
            int x1  = x0 + 1;
            i00 = (x0 ^ hy0) & (TSIZE - 1);
            i01 = (x0 ^ hy1) & (TSIZE - 1);
            i10 = (x1 ^ hy0) & (TSIZE - 1);
            i11 = (x1 ^ hy1) & (TSIZE - 1);
        } else {
            // dense: x*res + y (as the reference writes it)
            int base = x0 * res + y0;
            i00 = base;
            i01 = base + 1;
            i10 = base + res;
            i11 = base + res + 1;
        }

        float2 v00 = __ldg(&lat[i00 + off]);
        float2 v01 = __ldg(&lat[i01 + off]);
        float2 v10 = __ldg(&lat[i10 + off]);
        float2 v11 = __ldg(&lat[i11 + off]);

        float qx = 1.0f - px;
        float qy = 1.0f - py;
        float w00 = qx * qy;
        float w01 = qx * py;
        float w10 = px * qy;
        float w11 = px * py;

        r[2 * k + 0] = v00.x * w00 + v01.x * w01 + v10.x * w10 + v11.x * w11;
        r[2 * k + 1] = v00.y * w00 + v01.y * w01 + v10.y * w10 + v11.y * w11;
    }

    // out float4 index = n*8 + j = t  (4 floats per thread, fully coalesced)
    out[t] = make_float4(r[0], r[1], r[2], r[3]);
}

extern "C" void kernel_launch(void* const* d_in, const int* in_sizes, int n_in,
                              void* d_out, int out_size)
{
    const float2* uv  = (const float2*)d_in[0];
    const float2* lat = (const float2*)d_in[1];
    float4*       out = (float4*)d_out;

    const int total_threads = NPTS * 8;
    const int block = 256;
    const int grid  = total_threads / block;   // 32768

    hashgrid2d_kernel<<<grid, block>>>(uv, lat, out);
}

// round 2
// speedup vs baseline: 1.3165x; 1.3165x over previous
#include <cuda_runtime.h>

// HashGridEncoder2D: L=16, F=2, N=1048576, T=524288.
// Levels 0..11 dense, 12..15 hashed (prime 131101, mod 2^19).
//
// R2 strategy: repack dense-level tables into 32B "corner quads" so each
// dense-level lookup is ONE 256-bit load instead of four 64-bit gathers.
// L1tex wavefronts were the bottleneck (91% of peak) -> cut load count 64->28/pt.

#define NPTS    1048576
#define TSIZE   524288
#define HPRIME  131101
#define QTOTAL  659835   // sum of res^2 over dense levels 0..11

__constant__ int c_res[16] = {16, 22, 30, 42, 58, 80, 111, 153,
                              212, 294, 406, 561, 776, 1072, 1482, 2048};
__constant__ int c_off[16] = {0, 289, 818, 1779, 3628, 7109, 13670, 26214,
                              49930, 95299, 182324, 347973,
                              663817, 1188105, 1712393, 2236681};
// cumulative res^2 for dense levels (quad-cell offsets)
__constant__ int c_qoff[12] = {0, 256, 740, 1640, 3404, 6768, 13168,
                               25489, 48898, 93842, 180278, 345114};

// 21.1 MB quad table: cell (l,x,y) holds {v00, v01, v10, v11} as 8 floats.
__device__ __align__(32) float g_quads[(size_t)QTOTAL * 8];

__global__ void __launch_bounds__(256)
repack_kernel(const float2* __restrict__ lat)
{
    int c = blockIdx.x * blockDim.x + threadIdx.x;
    if (c >= QTOTAL) return;

    int l = 0;
#pragma unroll
    for (int i = 1; i < 12; i++) l += (c >= c_qoff[i]);

    int local = c - c_qoff[l];
    int res   = c_res[l];
    int x     = local / res;
    int y     = local - x * res;
    int base  = c_off[l] + x * res + y;

    float2 v00 = lat[base];
    float2 v01 = lat[base + 1];
    float2 v10 = lat[base + res];
    float2 v11 = lat[base + res + 1];

    float4* q = (float4*)(g_quads + (size_t)c * 8);
    q[0] = make_float4(v00.x, v00.y, v01.x, v01.y);
    q[1] = make_float4(v10.x, v10.y, v11.x, v11.y);
}

__global__ void __launch_bounds__(256)
hashgrid2d_kernel(const float2* __restrict__ uv,
                  const float2* __restrict__ lat,
                  float4* __restrict__ out)
{
    int t = blockIdx.x * blockDim.x + threadIdx.x;
    int n = t >> 3;          // point index
    int j = t & 7;           // level-pair index (levels 2j, 2j+1)
    if (n >= NPTS) return;

    float2 p = __ldg(&uv[n]);
    float r[4];

    if (j < 6) {
        // ---- two dense levels: one 256-bit quad load each ----
#pragma unroll
        for (int k = 0; k < 2; k++) {
            int l   = 2 * j + k;
            int res = c_res[l];

            float fres = (float)res;
            float sx = p.x * fres;
            float sy = p.y * fres;
            float fx = floorf(sx);
            float fy = floorf(sy);
            int   x0 = (int)fx;
            int   y0 = (int)fy;
            float px = sx - fx;
            float py = sy - fy;

            const float* qp = g_quads + (size_t)(c_qoff[l] + x0 * res + y0) * 8;
            float a0, a1, a2, a3, b0, b1, b2, b3;
            asm("ld.global.v8.f32 {%0,%1,%2,%3,%4,%5,%6,%7}, [%8];"
                : "=f"(a0), "=f"(a1), "=f"(a2), "=f"(a3),
                  "=f"(b0), "=f"(b1), "=f"(b2), "=f"(b3)
                : "l"(qp));

            float qx = 1.0f - px;
            float qy = 1.0f - py;
            float w00 = qx * qy;
            float w01 = qx * py;
            float w10 = px * qy;
            float w11 = px * py;

            r[2 * k + 0] = a0 * w00 + a2 * w01 + b0 * w10 + b2 * w11;
            r[2 * k + 1] = a1 * w00 + a3 * w01 + b1 * w10 + b3 * w11;
        }
    } else {
        // ---- two hashed levels: four scalar float2 gathers each ----
#pragma unroll
        for (int k = 0; k < 2; k++) {
            int l   = 12 + (j - 6) * 2 + k;
            int res = c_res[l];
            int off = c_off[l];

            float fres = (float)res;
            float sx = p.x * fres;
            float sy = p.y * fres;
            float fx = floorf(sx);
            float fy = floorf(sy);
            int   x0 = (int)fx;
            int   y0 = (int)fy;
            float px = sx - fx;
            float py = sy - fy;

            int hy0 = y0 * HPRIME;
            int hy1 = (y0 + 1) * HPRIME;
            int x1  = x0 + 1;
            int i00 = (x0 ^ hy0) & (TSIZE - 1);
            int i01 = (x0 ^ hy1) & (TSIZE - 1);
            int i10 = (x1 ^ hy0) & (TSIZE - 1);
            int i11 = (x1 ^ hy1) & (TSIZE - 1);

            float2 v00 = __ldg(&lat[i00 + off]);
            float2 v01 = __ldg(&lat[i01 + off]);
            float2 v10 = __ldg(&lat[i10 + off]);
            float2 v11 = __ldg(&lat[i11 + off]);

            float qx = 1.0f - px;
            float qy = 1.0f - py;
            float w00 = qx * qy;
            float w01 = qx * py;
            float w10 = px * qy;
            float w11 = px * py;

            r[2 * k + 0] = v00.x * w00 + v01.x * w01 + v10.x * w10 + v11.x * w11;
            r[2 * k + 1] = v00.y * w00 + v01.y * w01 + v10.y * w10 + v11.y * w11;
        }
    }

    out[t] = make_float4(r[0], r[1], r[2], r[3]);
}

extern "C" void kernel_launch(void* const* d_in, const int* in_sizes, int n_in,
                              void* d_out, int out_size)
{
    const float2* uv  = (const float2*)d_in[0];
    const float2* lat = (const float2*)d_in[1];
    float4*       out = (float4*)d_out;

    repack_kernel<<<(QTOTAL + 255) / 256, 256>>>(lat);

    const int total_threads = NPTS * 8;
    hashgrid2d_kernel<<<total_threads / 256, 256>>>(uv, lat, out);
}